// round 3
// baseline (speedup 1.0000x reference)
#include <cuda_runtime.h>
#include <cuda_bf16.h>
#include <cstddef>

// Problem shape (fixed):
//   logits [B, T, U+1, V] fp32, labels [B, U] int32, f_len [B], y_len [B]
#define Bk 8
#define Tk 256
#define Uk 64
#define U1k 65
#define Vk 1024
#define NEGF (-1e30f)

// Scratch (no allocations allowed -> device globals)
__device__ __align__(16) float g_blank[Bk * Tk * U1k];   // lp[..., 0]
__device__ __align__(16) float g_emit[Bk * Tk * Uk];     // lp[..., label], masked
__device__ float g_ll[Bk];

// ---------------------------------------------------------------------------
// Kernel 1: per-row logsumexp over V=1024; emit gather + length masking.
// One warp per (b,t,u) row; 8x float4 per lane, fully coalesced.
// (Measured at 77.6% DRAM / 6.15 TB/s -- at the bandwidth ceiling; unchanged.)
// ---------------------------------------------------------------------------
__global__ void __launch_bounds__(256) rnnt_softmax_kernel(
    const float* __restrict__ logits,
    const int* __restrict__ labels,
    const int* __restrict__ y_len)
{
    const int warp = (blockIdx.x * blockDim.x + threadIdx.x) >> 5;
    const int lane = threadIdx.x & 31;
    const int rows = Bk * Tk * U1k;
    if (warp >= rows) return;

    const int r = warp;
    const float4* p = reinterpret_cast<const float4*>(logits) + (size_t)r * (Vk / 4);

    float v[32];
    float m = NEGF;
#pragma unroll
    for (int k = 0; k < 8; ++k) {
        float4 f = p[lane + 32 * k];
        v[4 * k + 0] = f.x; v[4 * k + 1] = f.y;
        v[4 * k + 2] = f.z; v[4 * k + 3] = f.w;
        m = fmaxf(m, fmaxf(fmaxf(f.x, f.y), fmaxf(f.z, f.w)));
    }
#pragma unroll
    for (int o = 16; o; o >>= 1) m = fmaxf(m, __shfl_xor_sync(0xffffffffu, m, o));

    float s = 0.f;
#pragma unroll
    for (int i = 0; i < 32; ++i) s += __expf(v[i] - m);
#pragma unroll
    for (int o = 16; o; o >>= 1) s += __shfl_xor_sync(0xffffffffu, s, o);

    if (lane == 0) {
        const float lse = m + __logf(s);
        const int u  = r % U1k;
        const int bt = r / U1k;
        const int t  = bt % Tk;
        const int b  = bt / Tk;
        g_blank[r] = v[0] - lse;                 // element 0 is lane0's v[0]
        if (u < Uk) {
            float e;
            if (u < y_len[b]) {
                const int lab = labels[b * Uk + u];
                e = __ldg(logits + (size_t)r * Vk + lab) - lse;  // L1-resident row
            } else {
                e = NEGF;
            }
            g_emit[(b * Tk + t) * Uk + u] = e;
        }
    }
}

// logaddexp, safe for very negative finite operands
__device__ __forceinline__ float lae(float x, float y) {
    const float mx = fmaxf(x, y);
    const float mn = fminf(x, y);
    return mx + __logf(1.0f + __expf(mn - mx));
}

// ---------------------------------------------------------------------------
// Kernel 2: single-warp, barrier-free wavefront DP. One block per batch b.
// Lane l owns columns u=2l and u=2l+1; lane 31 also owns u=64.
// Per anti-diagonal d:
//   col 2l   needs col 2l-1 @ d-1  -> SHFL.UP of neighbor's odd column
//   col 2l+1 needs col 2l   @ d-1  -> own register
//   col 64   needs col 63   @ d-1  -> own register (lane 31)
// blank/emit staged into smem by 128 threads up front; loads during the DP
// have value-independent addresses so they sit off the serial chain.
// ---------------------------------------------------------------------------
__global__ void __launch_bounds__(128) rnnt_dp_kernel(
    const int* __restrict__ f_len,
    const int* __restrict__ y_len)
{
    extern __shared__ float sm[];
    float* s_blank = sm;               // Tk*U1k
    float* s_emit  = sm + Tk * U1k;    // Tk*Uk

    const int b   = blockIdx.x;
    const int tid = threadIdx.x;

    // Stage this batch's blank/emit into shared (all 128 threads, coalesced)
    {
        const float4* gb = reinterpret_cast<const float4*>(g_blank + b * Tk * U1k);
        float4* sb = reinterpret_cast<float4*>(s_blank);
        for (int i = tid; i < Tk * U1k / 4; i += 128) sb[i] = gb[i];
        const float4* ge = reinterpret_cast<const float4*>(g_emit + b * Tk * Uk);
        float4* se = reinterpret_cast<float4*>(s_emit);
        for (int i = tid; i < Tk * Uk / 4; i += 128) se[i] = ge[i];
    }
    __syncthreads();
    if (tid >= 32) return;             // only warp 0 runs the DP

    const int l  = tid;
    const int u0 = 2 * l;
    const int u1 = 2 * l + 1;
    const int fl = f_len[b];
    const int yl = y_len[b];

    float a0 = (u0 == 0) ? 0.f : NEGF;   // alpha[ , u0] at current diagonal
    float a1 = NEGF;                     // alpha[ , u1]
    float a2 = NEGF;                     // alpha[ , 64]  (lane 31 only)

#pragma unroll 4
    for (int d = 1; d <= (Tk - 1) + Uk; ++d) {
        // neighbor's odd column @ d-1 (left of u0). Must read before updating a1.
        const float leftlo = __shfl_up_sync(0xffffffffu, a1, 1);

        // ---- column u0 ----
        const int t0 = d - u0;
        float na0 = a0;
        if (u0 == 0) {
            if (t0 >= 1 && t0 < Tk) {
                na0 = a0 + s_blank[(t0 - 1) * U1k];
                if (t0 == fl - 1 && yl == 0) g_ll[b] = na0 + s_blank[(fl - 1) * U1k];
            }
        } else {
            if (t0 >= 1 && t0 < Tk) {
                na0 = lae(a0 + s_blank[(t0 - 1) * U1k + u0],
                          leftlo + s_emit[t0 * Uk + (u0 - 1)]);
                if (t0 == fl - 1 && u0 == yl) g_ll[b] = na0 + s_blank[(fl - 1) * U1k + u0];
            } else if (t0 == 0) {
                na0 = leftlo + s_emit[u0 - 1];           // row-0 cumsum
                if (fl == 1 && u0 == yl) g_ll[b] = na0 + s_blank[u0];
            }
        }

        // ---- column u1 (left neighbor is own a0 @ d-1) ----
        const int t1 = d - u1;
        float na1 = a1;
        if (t1 >= 1 && t1 < Tk) {
            na1 = lae(a1 + s_blank[(t1 - 1) * U1k + u1],
                      a0 + s_emit[t1 * Uk + (u1 - 1)]);
            if (t1 == fl - 1 && u1 == yl) g_ll[b] = na1 + s_blank[(fl - 1) * U1k + u1];
        } else if (t1 == 0) {
            na1 = a0 + s_emit[u1 - 1];
            if (fl == 1 && u1 == yl) g_ll[b] = na1 + s_blank[u1];
        }

        // ---- column 64 (lane 31; left neighbor is own a1 @ d-1) ----
        float na2 = a2;
        if (l == 31) {
            const int t2 = d - 64;
            if (t2 >= 1 && t2 < Tk) {
                na2 = lae(a2 + s_blank[(t2 - 1) * U1k + 64],
                          a1 + s_emit[t2 * Uk + 63]);
                if (t2 == fl - 1 && yl == 64) g_ll[b] = na2 + s_blank[(fl - 1) * U1k + 64];
            } else if (t2 == 0) {
                na2 = a1 + s_emit[63];
                if (fl == 1 && yl == 64) g_ll[b] = na2 + s_blank[64];
            }
        }

        a0 = na0; a1 = na1; a2 = na2;
    }
}

// ---------------------------------------------------------------------------
// Kernel 3: loss = -mean(ll)
// ---------------------------------------------------------------------------
__global__ void rnnt_finalize_kernel(float* __restrict__ out) {
    float s = 0.f;
#pragma unroll
    for (int b = 0; b < Bk; ++b) s += g_ll[b];
    out[0] = -s / (float)Bk;
}

extern "C" void kernel_launch(void* const* d_in, const int* in_sizes, int n_in,
                              void* d_out, int out_size)
{
    const float* logits = (const float*)d_in[0];
    const int*   labels = (const int*)d_in[1];
    const int*   f_len  = (const int*)d_in[2];
    const int*   y_len  = (const int*)d_in[3];

    const int rows = Bk * Tk * U1k;             // 133120 rows, one warp each
    const int blocks = (rows * 32 + 255) / 256; // 8 warps per block

    rnnt_softmax_kernel<<<blocks, 256>>>(logits, labels, y_len);

    const size_t smem = (size_t)(Tk * U1k + Tk * Uk) * sizeof(float);
    cudaFuncSetAttribute(rnnt_dp_kernel,
                         cudaFuncAttributeMaxDynamicSharedMemorySize, (int)smem);
    rnnt_dp_kernel<<<Bk, 128, smem>>>(f_len, y_len);

    rnnt_finalize_kernel<<<1, 1>>>((float*)d_out);
}

// round 4
// speedup vs baseline: 1.0792x; 1.0792x over previous
#include <cuda_runtime.h>
#include <cuda_bf16.h>
#include <cstddef>

// Problem shape (fixed):
//   logits [B, T, U+1, V] fp32, labels [B, U] int32, f_len [B], y_len [B]
#define Bk 8
#define Tk 256
#define Uk 64
#define U1k 65
#define Vk 1024
#define NEGF (-1e30f)

// Scratch (no allocations allowed -> device globals)
__device__ __align__(16) float g_blank[Bk * Tk * U1k];       // lp[..., 0]
__device__ __align__(16) float g_emitP[Bk * Tk * 66];        // col0=NEG, col u+1=emit[t][u]
__device__ float g_ll[Bk];
__device__ unsigned g_done;   // zero-initialized; reset by last block each run

// ---------------------------------------------------------------------------
// Kernel 1: per-row logsumexp over V=1024; emit gather + length masking.
// One warp per (b,t,u) row; 8x float4 per lane, fully coalesced.
// (Measured 77.6% DRAM / 6.15 TB/s — at the bandwidth ceiling; unchanged.)
// ---------------------------------------------------------------------------
__global__ void __launch_bounds__(256) rnnt_softmax_kernel(
    const float* __restrict__ logits,
    const int* __restrict__ labels,
    const int* __restrict__ y_len)
{
    const int warp = (blockIdx.x * blockDim.x + threadIdx.x) >> 5;
    const int lane = threadIdx.x & 31;
    const int rows = Bk * Tk * U1k;
    if (warp >= rows) return;

    const int r = warp;
    const float4* p = reinterpret_cast<const float4*>(logits) + (size_t)r * (Vk / 4);

    float v[32];
    float m = NEGF;
#pragma unroll
    for (int k = 0; k < 8; ++k) {
        float4 f = p[lane + 32 * k];
        v[4 * k + 0] = f.x; v[4 * k + 1] = f.y;
        v[4 * k + 2] = f.z; v[4 * k + 3] = f.w;
        m = fmaxf(m, fmaxf(fmaxf(f.x, f.y), fmaxf(f.z, f.w)));
    }
#pragma unroll
    for (int o = 16; o; o >>= 1) m = fmaxf(m, __shfl_xor_sync(0xffffffffu, m, o));

    float s = 0.f;
#pragma unroll
    for (int i = 0; i < 32; ++i) s += __expf(v[i] - m);
#pragma unroll
    for (int o = 16; o; o >>= 1) s += __shfl_xor_sync(0xffffffffu, s, o);

    if (lane == 0) {
        const float lse = m + __logf(s);
        const int u  = r % U1k;
        const int bt = r / U1k;
        const int t  = bt % Tk;
        const int b  = bt / Tk;
        g_blank[r] = v[0] - lse;                 // element 0 is lane0's v[0]
        if (u < Uk) {
            float e;
            if (u < y_len[b]) {
                const int lab = labels[b * Uk + u];
                e = __ldg(logits + (size_t)r * Vk + lab) - lse;  // L1-resident row
            } else {
                e = NEGF;
            }
            const int rowp = (b * Tk + t) * 66;
            g_emitP[rowp + u + 1] = e;
            if (u == 0) g_emitP[rowp] = NEGF;    // virtual column -1
        }
    }
}

// logaddexp, safe for very negative finite operands (mn-mx <= 0 always)
__device__ __forceinline__ float lae(float x, float y) {
    const float mx = fmaxf(x, y);
    const float mn = fminf(x, y);
    return mx + __logf(1.0f + __expf(mn - mx));
}

// ---------------------------------------------------------------------------
// Kernel 2: single-warp, BRANCH-FREE wavefront DP + fused finalize.
// One block per batch b. Lane l owns columns u=2l, 2l+1; lane 31 also u=64.
// Uniform cell update (predication only, no control flow):
//   x = a_prev + blank[clamp(t-1)][u]
//   y = left   + emitP[clamp(t)][u]        (emitP col 0 = NEG)
//   a = ((unsigned)t <= 255) ? lae(x,y) : a_prev
// t<=0 rows and u=0 column fall out of the same formula via NEG sentinels.
// ---------------------------------------------------------------------------
__global__ void __launch_bounds__(128) rnnt_dp_kernel(
    const int* __restrict__ f_len,
    const int* __restrict__ y_len,
    float* __restrict__ out)
{
    extern __shared__ float sm[];
    float* s_b = sm;                 // Tk*65
    float* s_e = sm + Tk * U1k;      // Tk*66
    __shared__ float s_ll;

    const int b   = blockIdx.x;
    const int tid = threadIdx.x;

    // Stage this batch's blank/emitP into shared (all 128 threads, coalesced)
    {
        const float4* gb = reinterpret_cast<const float4*>(g_blank + b * Tk * U1k);
        float4* sb = reinterpret_cast<float4*>(s_b);
        for (int i = tid; i < Tk * U1k / 4; i += 128) sb[i] = gb[i];
        const float4* ge = reinterpret_cast<const float4*>(g_emitP + b * Tk * 66);
        float4* se = reinterpret_cast<float4*>(s_e);
        for (int i = tid; i < Tk * 66 / 4; i += 128) se[i] = ge[i];
    }
    __syncthreads();
    if (tid >= 32) return;           // warp 0 runs the DP

    const int l  = tid;
    const int u0 = 2 * l;
    const int u1 = 2 * l + 1;
    const int fl = f_len[b];
    const int yl = y_len[b];

    // Loop-invariant extraction helpers: ll = alpha[fl-1][yl] + blank[fl-1][yl]
    const float bT0 = s_b[(fl - 1) * U1k + u0];
    const float bT1 = s_b[(fl - 1) * U1k + u1];
    const float bT2 = s_b[(fl - 1) * U1k + 64];
    const bool ex0 = (u0 == yl);
    const bool ex1 = (u1 == yl);
    const bool ex2 = (yl == 64) && (l == 31);
    const int dx0 = fl - 1 + u0;
    const int dx1 = fl - 1 + u1;
    const int dx2 = fl - 1 + 64;

    float a0 = (l == 0) ? 0.f : NEGF;
    float a1 = NEGF;
    float a2 = NEGF;

#pragma unroll 2
    for (int d = 1; d <= (Tk - 1) + Uk; ++d) {
        const float pa0 = a0, pa1 = a1, pa2 = a2;
        const float leftlo = __shfl_up_sync(0xffffffffu, pa1, 1);

        // ---- column u0 (left = neighbor's odd column) ----
        {
            const int t  = d - u0;
            const int tb = min(max(t - 1, 0), Tk - 1);
            const int te = min(max(t,     0), Tk - 1);
            const float x = pa0    + s_b[tb * U1k + u0];
            const float y = leftlo + s_e[te * 66  + u0];
            const float n = lae(x, y);
            a0 = ((unsigned)t <= 255u) ? n : pa0;
        }
        // ---- column u1 (left = own even column, pre-update) ----
        {
            const int t  = d - u1;
            const int tb = min(max(t - 1, 0), Tk - 1);
            const int te = min(max(t,     0), Tk - 1);
            const float x = pa1 + s_b[tb * U1k + u1];
            const float y = pa0 + s_e[te * 66  + u1];
            const float n = lae(x, y);
            a1 = ((unsigned)t <= 255u) ? n : pa1;
        }
        // ---- column 64 (meaningful on lane 31 only; uniform execution) ----
        {
            const int t  = d - 64;
            const int tb = min(max(t - 1, 0), Tk - 1);
            const int te = min(max(t,     0), Tk - 1);
            const float x = pa2 + s_b[tb * U1k + 64];
            const float y = pa1 + s_e[te * 66  + 64];
            const float n = lae(x, y);
            a2 = ((unsigned)t <= 255u) ? n : pa2;
        }

        // Extraction: exactly one (lane, column, d) fires per batch -> @P STS
        if (ex0 && d == dx0) s_ll = a0 + bT0;
        if (ex1 && d == dx1) s_ll = a1 + bT1;
        if (ex2 && d == dx2) s_ll = a2 + bT2;
    }

    __syncwarp();
    if (l == 0) {
        g_ll[b] = s_ll;
        __threadfence();
        const unsigned old = atomicAdd(&g_done, 1u);
        if (old == Bk - 1) {             // last block finalizes
            __threadfence();
            float s = 0.f;
#pragma unroll
            for (int i = 0; i < Bk; ++i) s += g_ll[i];
            out[0] = -s / (float)Bk;
            g_done = 0;                  // reset for next graph replay
        }
    }
}

extern "C" void kernel_launch(void* const* d_in, const int* in_sizes, int n_in,
                              void* d_out, int out_size)
{
    const float* logits = (const float*)d_in[0];
    const int*   labels = (const int*)d_in[1];
    const int*   f_len  = (const int*)d_in[2];
    const int*   y_len  = (const int*)d_in[3];

    const int rows = Bk * Tk * U1k;             // 133120 rows, one warp each
    const int blocks = (rows * 32 + 255) / 256; // 8 warps per block

    rnnt_softmax_kernel<<<blocks, 256>>>(logits, labels, y_len);

    const size_t smem = (size_t)(Tk * U1k + Tk * 66) * sizeof(float); // 134144 B
    cudaFuncSetAttribute(rnnt_dp_kernel,
                         cudaFuncAttributeMaxDynamicSharedMemorySize, (int)smem);
    rnnt_dp_kernel<<<Bk, 128, smem>>>(f_len, y_len, (float*)d_out);
}

// round 5
// speedup vs baseline: 1.0879x; 1.0081x over previous
#include <cuda_runtime.h>
#include <cuda_bf16.h>
#include <cstddef>

// Problem shape (fixed):
//   logits [B, T, U+1, V] fp32, labels [B, U] int32, f_len [B], y_len [B]
#define Bk 8
#define Tk 256
#define Uk 64
#define U1k 65
#define Vk 1024
#define NEGF  (-1e30f)
#define LOG2E 1.4426950408889634f
#define LN2   0.6931471805599453f
#define TP 392   // padded t-extent: [0,64)=front pad, [64,320)=rows 0..255, rest guard

// Scratch (device globals; no allocs allowed). Transposed, log2-scaled:
//   g_blankT[b][u][64+t]  = log2-softmax blank for (t,u)    (u = 0..64)
//   g_emitT [b][u][64+t]  = log2-softmax emit  for (t,u-1)  (row 0 = NEG sentinel)
// Front pad of emitT rows = NEG (written by DP block pre-pass); blankT pads are
// don't-care (never-written zeros are fine, see garbage-accumulation argument).
__device__ __align__(16) float g_blankT[Bk * U1k * TP];
__device__ __align__(16) float g_emitT [Bk * U1k * TP];
__device__ unsigned g_rows[Bk * Tk];   // per-(b,t) completed-row counters (65 each)
__device__ float    g_ll[Bk];
__device__ unsigned g_done;            // finalize ticket; reset each run

__device__ __forceinline__ float ex2f(float x){ float y; asm("ex2.approx.ftz.f32 %0,%1;":"=f"(y):"f"(x)); return y; }
__device__ __forceinline__ float lg2f(float x){ float y; asm("lg2.approx.ftz.f32 %0,%1;":"=f"(y):"f"(x)); return y; }

// log2-domain logaddexp: max + lg2(1 + 2^(min-max)). Safe for huge-negative args.
__device__ __forceinline__ float lae2(float x, float y) {
    const float mx = fmaxf(x, y);
    const float mn = fminf(x, y);
    return mx + lg2f(1.0f + ex2f(mn - mx));
}

// ---------------------------------------------------------------------------
// Producer role: one warp per (b,t,u) row; logsumexp over V=1024 (8x float4
// per lane, coalesced, at the BW ceiling). Writes transposed log2-scaled
// outputs, then fence + per-row counter increment.
// ---------------------------------------------------------------------------
__device__ void softmax_role(int sbid,
                             const float* __restrict__ logits,
                             const int* __restrict__ labels,
                             const int* __restrict__ y_len)
{
    const int warp = sbid * 8 + ((int)threadIdx.x >> 5);
    const int lane = threadIdx.x & 31;
    const int rows = Bk * Tk * U1k;
    if (warp >= rows) return;

    const int r = warp;
    const float4* p = reinterpret_cast<const float4*>(logits) + (size_t)r * (Vk / 4);

    float v[32];
    float m = NEGF;
#pragma unroll
    for (int k = 0; k < 8; ++k) {
        float4 f = p[lane + 32 * k];
        v[4*k+0] = f.x; v[4*k+1] = f.y; v[4*k+2] = f.z; v[4*k+3] = f.w;
        m = fmaxf(m, fmaxf(fmaxf(f.x, f.y), fmaxf(f.z, f.w)));
    }
#pragma unroll
    for (int o = 16; o; o >>= 1) m = fmaxf(m, __shfl_xor_sync(0xffffffffu, m, o));

    float s = 0.f;
#pragma unroll
    for (int i = 0; i < 32; ++i) s += __expf(v[i] - m);
#pragma unroll
    for (int o = 16; o; o >>= 1) s += __shfl_xor_sync(0xffffffffu, s, o);

    if (lane == 0) {
        const float lse = m + __logf(s);
        const int u  = r % U1k;
        const int bt = r / U1k;
        const int t  = bt % Tk;
        const int b  = bt / Tk;
        g_blankT[(b * U1k + u) * TP + 64 + t] = (v[0] - lse) * LOG2E;
        if (u < Uk) {
            float e;
            if (u < y_len[b]) {
                const int lab = labels[b * Uk + u];
                e = __ldg(logits + (size_t)r * Vk + lab) - lse;  // row is L1-hot
            } else {
                e = NEGF;
            }
            g_emitT[(b * U1k + (u + 1)) * TP + 64 + t] = e * LOG2E;
        }
        __threadfence();
        atomicAdd(&g_rows[b * Tk + t], 1u);
    }
}

// ---------------------------------------------------------------------------
// Consumer role: one block per batch. Warps 1-7 write emit NEG pads then exit;
// warp 0 runs the branch-free wavefront DP, trailing the producers via
// per-row counters checked once per 8-diagonal chunk. All data loads __ldcg
// (L2-coherent; L1 would be stale). Lane l owns u=2l,2l+1; all lanes mirror
// u=64 (broadcast loads, value used by lane 31).
// ---------------------------------------------------------------------------
__device__ void dp_role(int b, const int* __restrict__ f_len,
                        const int* __restrict__ y_len, float* __restrict__ out)
{
    const int tid = threadIdx.x;

    // Pre-pass: NEG sentinels for emitT (row 0 entirely; front pads rows 1..64).
    {
        float* eb = g_emitT + b * U1k * TP;
        for (int i = tid; i < TP; i += 256) eb[i] = NEGF * LOG2E;          // row 0
        for (int i = tid; i < 64 * 64; i += 256)
            eb[(1 + i / 64) * TP + (i % 64)] = NEGF * LOG2E;               // front pads
    }
    __syncthreads();
    if (tid >= 32) return;

    const int l  = tid;
    const int u0 = 2 * l;
    const int u1 = 2 * l + 1;
    const int fl = f_len[b];
    const int yl = y_len[b];

    const float* Bb = g_blankT + b * U1k * TP;
    const float* Eb = g_emitT  + b * U1k * TP;
    // Pointers at diagonal d: blank idx = 63 + d - u, emit idx = 64 + d - u.
    const float* pb0 = Bb + u0 * TP + 64 - u0;     // d=1
    const float* pe0 = Eb + u0 * TP + 65 - u0;
    const float* pb1 = Bb + u1 * TP + 64 - u1;
    const float* pe1 = Eb + u1 * TP + 65 - u1;
    const float* pb2 = Bb + 64 * TP + 0;
    const float* pe2 = Eb + 64 * TP + 1;

    // Extraction setup: ll = alpha[fl-1][yl] + blank[fl-1][yl], at d = fl-1+u.
    const bool ex0 = (u0 == yl);
    const bool ex1 = (u1 == yl);
    const bool ex2 = (l == 31) && (yl == 64);
    const int  dx0 = fl - 1 + u0, dx1 = fl - 1 + u1, dx2 = fl - 1 + 64;
    const float* pT0 = Bb + u0 * TP + 64 + fl - 1;
    const float* pT1 = Bb + u1 * TP + 64 + fl - 1;
    const float* pT2 = Bb + 64 * TP + 64 + fl - 1;

    float a0 = (l == 0) ? 0.f : NEGF;
    float a1 = NEGF, a2 = NEGF;
    float llr = 0.f;
    int t_chk = -1;

    for (int dc = 1; dc <= 320; dc += 8) {
        // Ensure rows <= min(dc+7,255) are produced (lane-parallel probe).
        const int t_hi = min(dc + 7, Tk - 1);
        if (t_chk < t_hi) {
            const int row  = t_chk + 1 + l;
            const bool nd  = (row <= t_hi);
            const unsigned* fp = &g_rows[b * Tk + (nd ? row : 0)];
            for (;;) {
                const unsigned c = nd ? __ldcg(fp) : 65u;
                if (__all_sync(0xffffffffu, c >= 65u)) break;
            }
            t_chk = t_hi;
        }
#pragma unroll
        for (int k = 0; k < 8; ++k) {
            const int d = dc + k;
            const float pa0 = a0, pa1 = a1, pa2 = a2;
            const float leftlo = __shfl_up_sync(0xffffffffu, pa1, 1);

            const float b0 = __ldcg(pb0 + k), e0 = __ldcg(pe0 + k);
            const float b1 = __ldcg(pb1 + k), e1 = __ldcg(pe1 + k);
            const float b2 = __ldcg(pb2 + k), e2 = __ldcg(pe2 + k);

            a0 = lae2(pa0 + b0, leftlo + e0);
            a1 = lae2(pa1 + b1, pa0    + e1);
            a2 = lae2(pa2 + b2, pa1    + e2);

            if (ex0 && d == dx0) llr = a0 + __ldcg(pT0);
            if (ex1 && d == dx1) llr = a1 + __ldcg(pT1);
            if (ex2 && d == dx2) llr = a2 + __ldcg(pT2);
        }
        pb0 += 8; pe0 += 8; pb1 += 8; pe1 += 8; pb2 += 8; pe2 += 8;
    }

    // Exactly one lane holds llr != 0-init; sum-reduce to lane 0.
#pragma unroll
    for (int o = 16; o; o >>= 1) llr += __shfl_xor_sync(0xffffffffu, llr, o);

    // Reset this batch's row counters for the next graph replay.
    for (int i = l; i < Tk; i += 32) g_rows[b * Tk + i] = 0u;
    __syncwarp();

    if (l == 0) {
        g_ll[b] = llr * LN2;
        __threadfence();
        const unsigned old = atomicAdd(&g_done, 1u);
        if (old == Bk - 1) {
            __threadfence();
            float s = 0.f;
#pragma unroll
            for (int i = 0; i < Bk; ++i) s += __ldcg(&g_ll[i]);
            out[0] = -s / (float)Bk;
            g_done = 0;
        }
    }
}

// ---------------------------------------------------------------------------
// Fused kernel: bids 0..7 = DP consumers (scheduled first, spin on counters),
// bids 8.. = softmax producers. No deadlock: consumers use 8 SMs / no smem.
// ---------------------------------------------------------------------------
__global__ void __launch_bounds__(256, 2) rnnt_fused_kernel(
    const float* __restrict__ logits,
    const int* __restrict__ labels,
    const int* __restrict__ f_len,
    const int* __restrict__ y_len,
    float* __restrict__ out)
{
    if (blockIdx.x < Bk) dp_role(blockIdx.x, f_len, y_len, out);
    else                 softmax_role(blockIdx.x - Bk, logits, labels, y_len);
}

extern "C" void kernel_launch(void* const* d_in, const int* in_sizes, int n_in,
                              void* d_out, int out_size)
{
    const float* logits = (const float*)d_in[0];
    const int*   labels = (const int*)d_in[1];
    const int*   f_len  = (const int*)d_in[2];
    const int*   y_len  = (const int*)d_in[3];

    const int rows = Bk * Tk * U1k;              // 133120 rows, 8 warps/block
    const int sblocks = (rows + 7) / 8;          // 16640 producer blocks
    rnnt_fused_kernel<<<Bk + sblocks, 256>>>(logits, labels, f_len, y_len,
                                             (float*)d_out);
}

// round 9
// speedup vs baseline: 1.7767x; 1.6331x over previous
#include <cuda_runtime.h>
#include <cuda_bf16.h>
#include <cstddef>

// Problem shape (fixed):
//   logits [B, T, U+1, V] fp32, labels [B, U] int32, f_len [B], y_len [B]
#define Bk 8
#define Tk 256
#define Uk 64
#define U1k 65
#define Vk 1024
#define NEGF  (-1e30f)
#define LOG2E 1.4426950408889634f
#define LN2   0.6931471805599453f
#define NEG2  (-1e30f)   // sentinel in log2 domain (magnitude irrelevant, finite)

// Scratch (device globals; no allocs). Transposed, log2-scaled:
//   g_blankT[b][u][t] = log2-softmax blank at (t,u),   u = 0..64
//   g_emitT [b][u][t] = log2-softmax emit  at (t, label u), u = 0..63 (masked)
__device__ __align__(16) float g_blankT[Bk * U1k * Tk];
__device__ __align__(16) float g_emitT [Bk * Uk  * Tk];
__device__ float    g_ll[Bk];
__device__ unsigned g_done;      // finalize ticket; reset each run

__device__ __forceinline__ float ex2f(float x){ float y; asm("ex2.approx.ftz.f32 %0,%1;":"=f"(y):"f"(x)); return y; }
__device__ __forceinline__ float lg2f(float x){ float y; asm("lg2.approx.ftz.f32 %0,%1;":"=f"(y):"f"(x)); return y; }

// log2-domain logaddexp: max + lg2(1 + 2^(min-max)); exact for NEG sentinels.
__device__ __forceinline__ float lae2(float x, float y) {
    const float mx = fmaxf(x, y);
    const float mn = fminf(x, y);
    return mx + lg2f(1.0f + ex2f(mn - mx));
}

// ---------------------------------------------------------------------------
// Kernel 1: per-row logsumexp over V=1024 (one warp per (b,t,u) row, 8x float4
// per lane, coalesced; measured 77.6% DRAM / 6.15 TB/s). Writes transposed,
// log2-scaled blank/emit tables.
// ---------------------------------------------------------------------------
__global__ void __launch_bounds__(256) rnnt_softmax_kernel(
    const float* __restrict__ logits,
    const int* __restrict__ labels,
    const int* __restrict__ y_len)
{
    const int warp = (blockIdx.x * blockDim.x + threadIdx.x) >> 5;
    const int lane = threadIdx.x & 31;
    const int rows = Bk * Tk * U1k;
    if (warp >= rows) return;

    const int r = warp;
    const float4* p = reinterpret_cast<const float4*>(logits) + (size_t)r * (Vk / 4);

    float v[32];
    float m = NEGF;
#pragma unroll
    for (int k = 0; k < 8; ++k) {
        float4 f = p[lane + 32 * k];
        v[4*k+0] = f.x; v[4*k+1] = f.y; v[4*k+2] = f.z; v[4*k+3] = f.w;
        m = fmaxf(m, fmaxf(fmaxf(f.x, f.y), fmaxf(f.z, f.w)));
    }
#pragma unroll
    for (int o = 16; o; o >>= 1) m = fmaxf(m, __shfl_xor_sync(0xffffffffu, m, o));

    float s = 0.f;
#pragma unroll
    for (int i = 0; i < 32; ++i) s += __expf(v[i] - m);
#pragma unroll
    for (int o = 16; o; o >>= 1) s += __shfl_xor_sync(0xffffffffu, s, o);

    if (lane == 0) {
        const float lse = m + __logf(s);
        const int u  = r % U1k;
        const int bt = r / U1k;
        const int t  = bt % Tk;
        const int b  = bt / Tk;
        g_blankT[(b * U1k + u) * Tk + t] = (v[0] - lse) * LOG2E;
        if (u < Uk) {
            float e;
            if (u < y_len[b]) {
                const int lab = labels[b * Uk + u];
                e = __ldg(logits + (size_t)r * Vk + lab) - lse;  // row is L1-hot
            } else {
                e = NEGF;
            }
            g_emitT[(b * Uk + u) * Tk + t] = e * LOG2E;
        }
    }
}

// ---------------------------------------------------------------------------
// Kernel 2: column-sweep DP via parallel semiring scan + fused finalize.
// One block (256 threads = 8 warps) per batch; thread owns t = tid.
// For u = 0..y_len[b]:   a[t] = lae(v[t], m[t] + a[t-1])
//   m[t] = blank[t-1][u] (m[0] never enters any path -> set 0)
//   v[t] = (u==0) ? (t==0 ? 0 : NEG) : a_prev[t] + emit[t][u-1]
// Scan op: (am,av) (+) (bm,bv) = (am+bm, lae(bv, bm+av))  [matches reference].
// 5-step Kogge-Stone per warp, warp totals through double-buffered smem
// (one __syncthreads per step), redundant 8-wide mini-scan for the prefix.
// Next u-row's loads are prefetched one step ahead (addresses value-free).
// ---------------------------------------------------------------------------
__global__ void __launch_bounds__(256) rnnt_dp_scan_kernel(
    const int* __restrict__ f_len,
    const int* __restrict__ y_len,
    float* __restrict__ out)
{
    __shared__ float2 tot[2][8];
    __shared__ float  s_ll;

    const int b    = blockIdx.x;
    const int t    = threadIdx.x;          // owned time index
    const int lane = t & 31;
    const int w    = t >> 5;

    const int fl = f_len[b];
    const int yl = y_len[b];

    const float* Bp = g_blankT + b * U1k * Tk;
    const float* Ep = g_emitT  + b * Uk  * Tk;
    const int tm1 = max(t - 1, 0);

    const float blank_ll = Bp[yl * Tk + (fl - 1)];   // lg2 blank at (fl-1, yl)

    float a_prev = 0.f;                 // alpha[t][u-1]; unused at u=0
    float mb = Bp[tm1];                 // blank row 0 -> m at u=0
    float me = 0.f;                     // emit row u-1; unused at u=0

    for (int u = 0; u <= yl; ++u) {
        // Prefetch next step's rows (blank row u+1, emit row u)
        const float nmb = Bp[min(u + 1, U1k - 1) * Tk + tm1];
        const float nme = Ep[min(u, Uk - 1) * Tk + t];

        float am = (t == 0) ? 0.f : mb;
        float av = (u == 0) ? ((t == 0) ? 0.f : NEG2) : (a_prev + me);

        // Intra-warp inclusive scan (5 steps)
#pragma unroll
        for (int o = 1; o < 32; o <<= 1) {
            const float sm_ = __shfl_up_sync(0xffffffffu, am, o);
            const float sv_ = __shfl_up_sync(0xffffffffu, av, o);
            if (lane >= o) { av = lae2(av, am + sv_); am += sm_; }
        }

        // Publish warp totals (lane 31), one barrier, double-buffered
        if (lane == 31) tot[u & 1][w] = make_float2(am, av);
        __syncthreads();

        // Redundant 8-wide scan of warp totals inside each warp
        float cm = 0.f, cv = NEG2;
        if (lane < 8) { const float2 tw = tot[u & 1][lane]; cm = tw.x; cv = tw.y; }
#pragma unroll
        for (int o = 1; o < 8; o <<= 1) {
            const float sm_ = __shfl_up_sync(0xffffffffu, cm, o);
            const float sv_ = __shfl_up_sync(0xffffffffu, cv, o);
            if (lane >= o && lane < 8) { cv = lae2(cv, cm + sv_); cm += sm_; }
        }
        const float Pv = __shfl_sync(0xffffffffu, cv, (w == 0) ? 0 : (w - 1));
        const float af = (w == 0) ? av : lae2(av, am + Pv);

        if (u == yl && t == fl - 1) s_ll = af + blank_ll;

        a_prev = af;
        mb = nmb; me = nme;
    }

    __syncthreads();
    if (t == 0) {
        g_ll[b] = s_ll * LN2;
        __threadfence();
        const unsigned old = atomicAdd(&g_done, 1u);
        if (old == Bk - 1) {            // last block finalizes
            __threadfence();
            float s = 0.f;
#pragma unroll
            for (int i = 0; i < Bk; ++i) s += __ldcg(&g_ll[i]);
            out[0] = -s / (float)Bk;
            g_done = 0;                 // reset for next graph replay
        }
    }
}

extern "C" void kernel_launch(void* const* d_in, const int* in_sizes, int n_in,
                              void* d_out, int out_size)
{
    const float* logits = (const float*)d_in[0];
    const int*   labels = (const int*)d_in[1];
    const int*   f_len  = (const int*)d_in[2];
    const int*   y_len  = (const int*)d_in[3];

    const int rows = Bk * Tk * U1k;             // 133120 rows, one warp each
    const int blocks = (rows * 32 + 255) / 256; // 8 warps per block

    rnnt_softmax_kernel<<<blocks, 256>>>(logits, labels, y_len);
    rnnt_dp_scan_kernel<<<Bk, 256>>>(f_len, y_len, (float*)d_out);
}